// round 2
// baseline (speedup 1.0000x reference)
#include <cuda_runtime.h>
#include <cuda_bf16.h>
#include <math.h>

// Problem dims (fixed by the dataset)
#define SS 128      // sequence length
#define BB 64       // batch
#define HH 1024     // hidden = embedding dim
#define VV 10000    // vocab
#define MM (SS*BB)  // 8192 rows for the batched GEMMs
#define BH (BB*HH)  // 65536

// ---------------- device scratch (no allocations allowed) ----------------
__device__ float g_pre0[MM * HH];   // precomputed emb@W_ih0^T + b_ih0 for all steps
__device__ float g_X[MM * HH];      // layer-1 outputs for all steps (input to logits GEMM)
__device__ float g_h0[2][BH];       // ping-pong layer-0 hidden
__device__ float g_h1[2][BH];       // ping-pong layer-1 hidden
__device__ float g_acc0[BH];        // partial-sum accumulator for layer 0
__device__ float g_acc1[BH];        // partial-sum accumulator for layer 1

// ---------------- generic tiled fp32 GEMM: C = A @ B^T + bias ----------------
// A: [M,K] row-major (or gathered rows of emb when GATHER), B: [N,K] row-major.
// BM=BN=128, BK=16, 256 threads, 8x8 per thread. M must be a multiple of 128,
// K a multiple of 16; N is bounds-checked (needed for V=10000).
template<bool GATHER>
__global__ void __launch_bounds__(256) sgemm_tn(
    const float* __restrict__ A,
    const float* __restrict__ emb,
    const int*   __restrict__ gidx,
    float scaleA,
    const float* __restrict__ Bm,
    const float* __restrict__ bias,
    float* __restrict__ C, int ldc,
    int N, int K)
{
    __shared__ float As[16][128 + 4];
    __shared__ float Bs[16][128 + 4];

    const int bm = blockIdx.y * 128;
    const int bn = blockIdx.x * 128;
    const int tid = threadIdx.x;
    const int tx = tid & 15;        // n-group
    const int ty = tid >> 4;        // m-group
    const int lr0 = tid >> 2;       // 0..63
    const int lr1 = lr0 + 64;       // 64..127
    const int lc4 = (tid & 3) * 4;  // 0,4,8,12

    const float* arow0;
    const float* arow1;
    if (GATHER) {
        arow0 = emb + (size_t)gidx[bm + lr0] * K;
        arow1 = emb + (size_t)gidx[bm + lr1] * K;
    } else {
        arow0 = A + (size_t)(bm + lr0) * K;
        arow1 = A + (size_t)(bm + lr1) * K;
    }
    const int  bn0 = bn + lr0, bn1 = bn + lr1;
    const bool v0 = bn0 < N, v1 = bn1 < N;
    const float* brow0 = Bm + (size_t)bn0 * K;
    const float* brow1 = Bm + (size_t)bn1 * K;

    float acc[8][8] = {};

    for (int k0 = 0; k0 < K; k0 += 16) {
        float4 a0 = *(const float4*)(arow0 + k0 + lc4);
        float4 a1 = *(const float4*)(arow1 + k0 + lc4);
        if (GATHER) {
            a0.x *= scaleA; a0.y *= scaleA; a0.z *= scaleA; a0.w *= scaleA;
            a1.x *= scaleA; a1.y *= scaleA; a1.z *= scaleA; a1.w *= scaleA;
        }
        float4 b0 = v0 ? *(const float4*)(brow0 + k0 + lc4) : make_float4(0.f,0.f,0.f,0.f);
        float4 b1 = v1 ? *(const float4*)(brow1 + k0 + lc4) : make_float4(0.f,0.f,0.f,0.f);

        As[lc4+0][lr0] = a0.x; As[lc4+1][lr0] = a0.y; As[lc4+2][lr0] = a0.z; As[lc4+3][lr0] = a0.w;
        As[lc4+0][lr1] = a1.x; As[lc4+1][lr1] = a1.y; As[lc4+2][lr1] = a1.z; As[lc4+3][lr1] = a1.w;
        Bs[lc4+0][lr0] = b0.x; Bs[lc4+1][lr0] = b0.y; Bs[lc4+2][lr0] = b0.z; Bs[lc4+3][lr0] = b0.w;
        Bs[lc4+0][lr1] = b1.x; Bs[lc4+1][lr1] = b1.y; Bs[lc4+2][lr1] = b1.z; Bs[lc4+3][lr1] = b1.w;
        __syncthreads();

        #pragma unroll
        for (int kk = 0; kk < 16; kk++) {
            float4 av0 = *(const float4*)&As[kk][ty*8];
            float4 av1 = *(const float4*)&As[kk][ty*8 + 4];
            float4 bw0 = *(const float4*)&Bs[kk][tx*8];
            float4 bw1 = *(const float4*)&Bs[kk][tx*8 + 4];
            float a[8] = {av0.x, av0.y, av0.z, av0.w, av1.x, av1.y, av1.z, av1.w};
            float b[8] = {bw0.x, bw0.y, bw0.z, bw0.w, bw1.x, bw1.y, bw1.z, bw1.w};
            #pragma unroll
            for (int i = 0; i < 8; i++)
                #pragma unroll
                for (int j = 0; j < 8; j++)
                    acc[i][j] = fmaf(a[i], b[j], acc[i][j]);
        }
        __syncthreads();
    }

    #pragma unroll
    for (int i = 0; i < 8; i++) {
        const int m = bm + ty*8 + i;
        #pragma unroll
        for (int j = 0; j < 8; j++) {
            const int n = bn + tx*8 + j;
            if (n < N) C[(size_t)m * ldc + n] = acc[i][j] + bias[n];
        }
    }
}

// ---------------- recurrence partial GEMM: acc[b][j] += h[b,:]·W[j,:] over a K-chunk ----
// h: [64,1024], W: [1024,1024] row-major [j][k]. grid = (16 j-tiles, 8 k-chunks of 128).
// Block: 256 threads, 64x64 output tile, 4x4 per thread, atomicAdd epilogue.
__global__ void __launch_bounds__(256) step_gemm(
    const float* __restrict__ h,
    const float* __restrict__ W,
    float* __restrict__ acc)
{
    const int jb = blockIdx.x * 64;
    const int k0 = blockIdx.y * 128;
    __shared__ float Hs[16][64 + 4];
    __shared__ float Ws[16][64 + 4];

    const int tid = threadIdx.x;
    const int tx = tid & 15;        // 4 j each
    const int ty = tid >> 4;        // 4 b each
    const int lr  = tid >> 2;       // 0..63
    const int lc4 = (tid & 3) * 4;  // 0,4,8,12

    float r[4][4] = {};

    #pragma unroll
    for (int kt = 0; kt < 128; kt += 16) {
        float4 hv = *(const float4*)(h + (size_t)lr * HH + k0 + kt + lc4);
        float4 wv = *(const float4*)(W + (size_t)(jb + lr) * HH + k0 + kt + lc4);
        Hs[lc4+0][lr] = hv.x; Hs[lc4+1][lr] = hv.y; Hs[lc4+2][lr] = hv.z; Hs[lc4+3][lr] = hv.w;
        Ws[lc4+0][lr] = wv.x; Ws[lc4+1][lr] = wv.y; Ws[lc4+2][lr] = wv.z; Ws[lc4+3][lr] = wv.w;
        __syncthreads();
        #pragma unroll
        for (int kk = 0; kk < 16; kk++) {
            float4 h4 = *(const float4*)&Hs[kk][ty*4];
            float4 w4 = *(const float4*)&Ws[kk][tx*4];
            float hb[4] = {h4.x, h4.y, h4.z, h4.w};
            float wj[4] = {w4.x, w4.y, w4.z, w4.w};
            #pragma unroll
            for (int i = 0; i < 4; i++)
                #pragma unroll
                for (int j = 0; j < 4; j++)
                    r[i][j] = fmaf(hb[i], wj[j], r[i][j]);
        }
        __syncthreads();
    }

    #pragma unroll
    for (int i = 0; i < 4; i++)
        #pragma unroll
        for (int j = 0; j < 4; j++)
            atomicAdd(&acc[(size_t)(ty*4 + i) * HH + jb + tx*4 + j], r[i][j]);
}

// ---------------- bias + tanh + buffer plumbing ----------------
__global__ void __launch_bounds__(256) step_tanh(
    float* __restrict__ acc,
    const float* __restrict__ pre,    // optional (layer 0: pre0 slab)
    const float* __restrict__ bias1,
    const float* __restrict__ bias2,  // optional
    float* __restrict__ hout,
    float* __restrict__ xout)         // optional (layer 1: X[t] slab)
{
    const int i = blockIdx.x * 256 + threadIdx.x;  // grid covers 65536
    const int j = i & (HH - 1);
    float v = acc[i] + bias1[j];
    if (pre)   v += pre[i];
    if (bias2) v += bias2[j];
    v = tanhf(v);
    acc[i] = 0.0f;
    hout[i] = v;
    if (xout) xout[i] = v;
}

__global__ void __launch_bounds__(256) init_kernel(
    const float* __restrict__ hidden, float* h0, float* h1, float* a0, float* a1)
{
    const int i = blockIdx.x * 256 + threadIdx.x;
    h0[i] = hidden[i];
    h1[i] = hidden[BH + i];
    a0[i] = 0.0f;
    a1[i] = 0.0f;
}

__global__ void __launch_bounds__(256) final_kernel(
    const float* __restrict__ h0, const float* __restrict__ h1, float* __restrict__ out)
{
    const int i = blockIdx.x * 256 + threadIdx.x;
    out[i] = h0[i];
    out[BH + i] = h1[i];
}

// ---------------- launcher ----------------
extern "C" void kernel_launch(void* const* d_in, const int* in_sizes, int n_in,
                              void* d_out, int out_size)
{
    const int*   inputs = (const int*)  d_in[0];  // [S,B]
    const float* hidden = (const float*)d_in[1];  // [L,B,H]
    const float* emb    = (const float*)d_in[2];  // [V,E]
    const float* W_ih   = (const float*)d_in[3];  // [L,H,E]
    const float* b_ih   = (const float*)d_in[4];  // [L,H]
    const float* W_hh   = (const float*)d_in[5];  // [L,H,H]
    const float* b_hh   = (const float*)d_in[6];  // [L,H]
    const float* W_out  = (const float*)d_in[7];  // [V,H]
    const float* b_out  = (const float*)d_in[8];  // [V]

    const float* W_ih0 = W_ih;
    const float* W_ih1 = W_ih + (size_t)HH * HH;
    const float* W_hh0 = W_hh;
    const float* W_hh1 = W_hh + (size_t)HH * HH;
    const float* b_ih0 = b_ih;
    const float* b_ih1 = b_ih + HH;
    const float* b_hh0 = b_hh;
    const float* b_hh1 = b_hh + HH;

    float *pre0, *X, *h0base, *h1base, *acc0, *acc1;
    cudaGetSymbolAddress((void**)&pre0,  g_pre0);
    cudaGetSymbolAddress((void**)&X,     g_X);
    cudaGetSymbolAddress((void**)&h0base, g_h0);
    cudaGetSymbolAddress((void**)&h1base, g_h1);
    cudaGetSymbolAddress((void**)&acc0,  g_acc0);
    cudaGetSymbolAddress((void**)&acc1,  g_acc1);
    float* h0b[2] = {h0base, h0base + BH};
    float* h1b[2] = {h1base, h1base + BH};

    float* out = (float*)d_out;

    // init hidden + zero accumulators
    init_kernel<<<BH/256, 256>>>(hidden, h0b[0], h1b[0], acc0, acc1);

    // Phase A: pre0[m][j] = (emb[tok[m]]*sqrt(E)) @ W_ih0^T + b_ih0   (M=8192,N=1024,K=1024)
    {
        dim3 g(HH/128, MM/128);
        sgemm_tn<true><<<g, 256>>>(nullptr, emb, inputs, 32.0f,
                                   W_ih0, b_ih0, pre0, HH, HH, HH);
    }

    // Phase B: sequential recurrence
    dim3 gs(16, 8);  // 16 j-tiles x 8 k-chunks of 128
    for (int t = 0; t < SS; t++) {
        const int cur = t & 1, nxt = 1 - cur;
        // layer 0 recurrent term + layer 1 recurrent term (independent of layer-0 output)
        step_gemm<<<gs, 256>>>(h0b[cur], W_hh0, acc0);
        step_gemm<<<gs, 256>>>(h1b[cur], W_hh1, acc1);
        // layer 0 activation: h0_new = tanh(pre0[t] + acc0 + b_hh0)
        step_tanh<<<BH/256, 256>>>(acc0, pre0 + (size_t)t * BH, b_hh0, nullptr,
                                   h0b[nxt], nullptr);
        // layer 1 input term from fresh h0_new
        step_gemm<<<gs, 256>>>(h0b[nxt], W_ih1, acc1);
        // layer 1 activation: h1_new = tanh(acc1 + b_ih1 + b_hh1); also stash into X[t]
        step_tanh<<<BH/256, 256>>>(acc1, nullptr, b_ih1, b_hh1,
                                   h1b[nxt], X + (size_t)t * BH);
    }

    // Phase C: logits = X @ W_out^T + b_out   (M=8192, N=10000, K=1024)
    {
        dim3 g((VV + 127) / 128, MM / 128);
        sgemm_tn<false><<<g, 256>>>(X, nullptr, nullptr, 1.0f,
                                    W_out, b_out, out, VV, VV, HH);
    }

    // h_final = [h0, h1] after the last step (buffers with index S%2 == 0)
    const long long logitsN = (long long)MM * VV;
    if ((long long)out_size >= logitsN + 2LL * BH) {
        final_kernel<<<BH/256, 256>>>(h0b[0], h1b[0], out + logitsN);
    }
}